// round 14
// baseline (speedup 1.0000x reference)
#include <cuda_runtime.h>

// Per-pixel dynamic conv (KPN style), K=5. B=4, C=64, H=128, W=128.
// out[b,c,h,w] = sum_t core[b,t,c,h,w] * data_pad[b,c,h+t/5-2, w+t%5-2]
// Pure HBM stream: core = 419 MB read-once; min traffic 453 MB.
//
// R8 = R6 champion config (256 thr, occ 4, 5 front-batched __ldcs/di-row)
//      with shuffle-based data halo: lane == w4 exactly spans a W-row, so
//      each lane does ONE coalesced LDG.128 and gets the +/-2 halo from
//      neighbor lanes via shfl. Kills the w_interior divergence (R6 made
//      EVERY warp run both fast+slow paths) and cuts data loads 3->1.
// Ceiling established: ~85.5-86% DRAM / 6.8 TB/s; MLP/occ/prefetch/block-
// size levers exhausted (R3/R4/R5/R7).

#define KS 5
#define PAD 2

namespace {
constexpr int B = 4, C = 64, H = 128, W = 128;
constexpr int HW = H * W;
constexpr int CHW = C * HW;
constexpr int TAPS = KS * KS;
}

__global__ __launch_bounds__(256, 4)
void dynconv_kernel(const float* __restrict__ data,
                    const float* __restrict__ core,
                    float* __restrict__ out) {
    int idx = blockIdx.x * 256 + threadIdx.x;   // over B*C*H*(W/4) = 1048576

    int lane = threadIdx.x & 31;    // == w4: lanes span one full W-row
    int h  = (idx >> 5) & (H - 1);
    int c  = (idx >> 12) & (C - 1);
    int b  = idx >> 18;
    int w0 = lane << 2;

    const float* dbase = data + ((long)(b * C + c)) * HW;
    const float* cbase = core + ((long)(b * TAPS) * C + c) * HW + h * W + w0;

    float4 acc = make_float4(0.f, 0.f, 0.f, 0.f);

    #pragma unroll
    for (int di = 0; di < KS; di++) {
        int hh = h + di - PAD;
        const float* cp = cbase + (long)(di * KS) * CHW;

        // ---- 5 back-to-back streaming core loads (the DRAM stream) ----
        float4 c0 = __ldcs(reinterpret_cast<const float4*>(cp));
        float4 c1 = __ldcs(reinterpret_cast<const float4*>(cp + (long)CHW));
        float4 c2 = __ldcs(reinterpret_cast<const float4*>(cp + (long)CHW * 2));
        float4 c3 = __ldcs(reinterpret_cast<const float4*>(cp + (long)CHW * 3));
        float4 c4 = __ldcs(reinterpret_cast<const float4*>(cp + (long)CHW * 4));

        // ---- data row: 1 lane-local LDG.128 (warp-uniform hh branch) ----
        float4 m = make_float4(0.f, 0.f, 0.f, 0.f);
        if (hh >= 0 && hh < H)
            m = *reinterpret_cast<const float4*>(dbase + hh * W + w0);

        // halo via shuffles; w-boundary == warp-boundary -> zeros at edges
        float r0 = __shfl_up_sync(0xffffffffu, m.z, 1);   // data[w0-2]
        float r1 = __shfl_up_sync(0xffffffffu, m.w, 1);   // data[w0-1]
        float r6 = __shfl_down_sync(0xffffffffu, m.x, 1); // data[w0+4]
        float r7 = __shfl_down_sync(0xffffffffu, m.y, 1); // data[w0+5]
        if (lane == 0)  { r0 = 0.f; r1 = 0.f; }
        if (lane == 31) { r6 = 0.f; r7 = 0.f; }

        // row[0..7] = { r0, r1, m.x, m.y, m.z, m.w, r6, r7 }
        // consume: output col mcol of tap dj uses row[mcol + dj]
        acc.x += c0.x * r0;  acc.y += c0.y * r1;  acc.z += c0.z * m.x; acc.w += c0.w * m.y;
        acc.x += c1.x * r1;  acc.y += c1.y * m.x; acc.z += c1.z * m.y; acc.w += c1.w * m.z;
        acc.x += c2.x * m.x; acc.y += c2.y * m.y; acc.z += c2.z * m.z; acc.w += c2.w * m.w;
        acc.x += c3.x * m.y; acc.y += c3.y * m.z; acc.z += c3.z * m.w; acc.w += c3.w * r6;
        acc.x += c4.x * m.z; acc.y += c4.y * m.w; acc.z += c4.z * r6;  acc.w += c4.w * r7;
    }

    __stcs(reinterpret_cast<float4*>(out + (long)idx * 4), acc);
}

extern "C" void kernel_launch(void* const* d_in, const int* in_sizes, int n_in,
                              void* d_out, int out_size) {
    const float* data = (const float*)d_in[0];  // [4,64,128,128]
    const float* core = (const float*)d_in[1];  // [4,1600,128,128]
    float* out = (float*)d_out;                 // [4,64,128,128]

    int total4 = B * C * H * (W / 4);           // 1048576
    dynconv_kernel<<<total4 / 256, 256>>>(data, core, out);
}